// round 2
// baseline (speedup 1.0000x reference)
#include <cuda_runtime.h>

#define BATCH 32768

// ---------------- scratch (static device globals; no allocs allowed) ----------------
__device__ __align__(16) float g_buf0[BATCH * 1024];
__device__ __align__(16) float g_buf1[BATCH * 1024];
__device__ __align__(16) float g_x4n [BATCH * 512];
__device__ __align__(16) float g_wn[512];
__device__ __align__(16) float g_wl[512];
__device__ float g_sc[2];   // [0]=bn (mean of nb5), [1]=bl (wreg . lb5)

// ---------------- head-collapse precompute ----------------
// w_n[k] = mean_o nW5[o,k]          (nW5: [256,512])
// w_l[k] = sum_o wreg[o]*lW5[o,k]   (lW5: [256,512], wreg: [256])
__global__ void precompute_head(const float* __restrict__ nW5, const float* __restrict__ nb5,
                                const float* __restrict__ lW5, const float* __restrict__ lb5,
                                const float* __restrict__ wreg)
{
    int k = threadIdx.x;                // 512 threads
    float s1 = 0.f, s2 = 0.f;
    #pragma unroll 4
    for (int o = 0; o < 256; ++o) {
        s1 += nW5[o * 512 + k];
        s2 += wreg[o] * lW5[o * 512 + k];
    }
    g_wn[k] = s1 * (1.f / 256.f);
    g_wl[k] = s2;
    if (k == 0) {
        float b = 0.f;
        for (int o = 0; o < 256; ++o) b += nb5[o];
        g_sc[0] = b * (1.f / 256.f);
    }
    if (k == 1) {
        float b = 0.f;
        for (int o = 0; o < 256; ++o) b += wreg[o] * lb5[o];
        g_sc[1] = b;
    }
}

// ---------------- fp32 GEMM: C[M,N] = relu?(A[M,K] @ W[N,K]^T + bias[N]) ----------------
// BM=BN=128, BK=16, 256 threads, 8x8 per-thread tile.
// Requires M%128==0, N%128==0, K%16==0 (holds for all 8 calls).
template <bool RELU>
__global__ __launch_bounds__(256, 2)
void gemm_btrans(const float* __restrict__ A, const float* __restrict__ W,
                 const float* __restrict__ bias, float* __restrict__ C,
                 int M, int N, int K)
{
    constexpr int BM = 128, BN = 128, BK = 16;
    __shared__ __align__(16) float As[BK][BM];
    __shared__ __align__(16) float Bs[BK][BN];

    const int t  = threadIdx.x;
    const int bm = blockIdx.y * BM;
    const int bn = blockIdx.x * BN;
    const int tx = t & 15;          // 0..15 -> col group
    const int ty = t >> 4;          // 0..15 -> row group

    // tile loads: 128 rows x 16 cols = 512 float4; 2 per thread
    const int r0 = t >> 2;          // 0..63  (first half rows), +64 for second
    const int c4 = (t & 3) * 4;     // k-offset within BK

    float acc[8][8] = {};

    for (int k0 = 0; k0 < K; k0 += BK) {
        // load A tile (transposed into As[k][m])
        #pragma unroll
        for (int h = 0; h < 2; ++h) {
            int row = r0 + h * 64;
            float4 v = *(const float4*)(A + (long)(bm + row) * K + k0 + c4);
            As[c4 + 0][row] = v.x; As[c4 + 1][row] = v.y;
            As[c4 + 2][row] = v.z; As[c4 + 3][row] = v.w;
        }
        // load W tile (transposed into Bs[k][n])
        #pragma unroll
        for (int h = 0; h < 2; ++h) {
            int row = r0 + h * 64;
            float4 v = *(const float4*)(W + (long)(bn + row) * K + k0 + c4);
            Bs[c4 + 0][row] = v.x; Bs[c4 + 1][row] = v.y;
            Bs[c4 + 2][row] = v.z; Bs[c4 + 3][row] = v.w;
        }
        __syncthreads();

        #pragma unroll
        for (int k = 0; k < BK; ++k) {
            float a[8], b[8];
            *(float4*)(a)     = *(const float4*)&As[k][ty * 8];
            *(float4*)(a + 4) = *(const float4*)&As[k][ty * 8 + 4];
            *(float4*)(b)     = *(const float4*)&Bs[k][tx * 8];
            *(float4*)(b + 4) = *(const float4*)&Bs[k][tx * 8 + 4];
            #pragma unroll
            for (int i = 0; i < 8; ++i)
                #pragma unroll
                for (int j = 0; j < 8; ++j)
                    acc[i][j] = fmaf(a[i], b[j], acc[i][j]);
        }
        __syncthreads();
    }

    // epilogue: bias + relu, float4 stores
    float bv[8];
    #pragma unroll
    for (int j = 0; j < 8; ++j) bv[j] = bias[bn + tx * 8 + j];

    #pragma unroll
    for (int i = 0; i < 8; ++i) {
        long row = bm + ty * 8 + i;
        float out[8];
        #pragma unroll
        for (int j = 0; j < 8; ++j) {
            float v = acc[i][j] + bv[j];
            out[j] = RELU ? fmaxf(v, 0.f) : v;
        }
        *(float4*)(C + row * N + bn + tx * 8)     = *(float4*)(out);
        *(float4*)(C + row * N + bn + tx * 8 + 4) = *(float4*)(out + 4);
    }
}

// ---------------- fused head: out[b] = (x4n[b].wn + bn) * (x4l[b].wl + bl) ----------------
__global__ __launch_bounds__(256)
void head_kernel(const float* __restrict__ xn, const float* __restrict__ xl,
                 float* __restrict__ out)
{
    int warp = (blockIdx.x * 256 + threadIdx.x) >> 5;
    int lane = threadIdx.x & 31;
    if (warp >= BATCH) return;

    const float4* pn = (const float4*)(xn + (long)warp * 512);
    const float4* pl = (const float4*)(xl + (long)warp * 512);
    const float4* wn = (const float4*)g_wn;
    const float4* wl = (const float4*)g_wl;

    float sn = 0.f, sl = 0.f;
    #pragma unroll
    for (int i = lane; i < 128; i += 32) {
        float4 a = pn[i], w = wn[i];
        sn += a.x * w.x + a.y * w.y + a.z * w.z + a.w * w.w;
        float4 b = pl[i], v = wl[i];
        sl += b.x * v.x + b.y * v.y + b.z * v.z + b.w * v.w;
    }
    #pragma unroll
    for (int off = 16; off > 0; off >>= 1) {
        sn += __shfl_xor_sync(0xffffffffu, sn, off);
        sl += __shfl_xor_sync(0xffffffffu, sl, off);
    }
    if (lane == 0)
        out[warp] = (sn + g_sc[0]) * (sl + g_sc[1]);
}

// ---------------- launch ----------------
extern "C" void kernel_launch(void* const* d_in, const int* in_sizes, int n_in,
                              void* d_out, int out_size)
{
    const float* node_x = (const float*)d_in[0];   // [B,256]
    const float* layer_x= (const float*)d_in[1];   // [B,16]
    const float* nW1 = (const float*)d_in[2];  const float* nb1 = (const float*)d_in[3];
    const float* nW2 = (const float*)d_in[4];  const float* nb2 = (const float*)d_in[5];
    const float* nW3 = (const float*)d_in[6];  const float* nb3 = (const float*)d_in[7];
    const float* nW4 = (const float*)d_in[8];  const float* nb4 = (const float*)d_in[9];
    const float* nW5 = (const float*)d_in[10]; const float* nb5 = (const float*)d_in[11];
    const float* lW1 = (const float*)d_in[12]; const float* lb1 = (const float*)d_in[13];
    const float* lW2 = (const float*)d_in[14]; const float* lb2 = (const float*)d_in[15];
    const float* lW3 = (const float*)d_in[16]; const float* lb3 = (const float*)d_in[17];
    const float* lW4 = (const float*)d_in[18]; const float* lb4 = (const float*)d_in[19];
    const float* lW5 = (const float*)d_in[20]; const float* lb5 = (const float*)d_in[21];
    const float* wreg= (const float*)d_in[22]; // [256]
    float* out = (float*)d_out;

    float *buf0, *buf1, *x4n;
    cudaGetSymbolAddress((void**)&buf0, g_buf0);
    cudaGetSymbolAddress((void**)&buf1, g_buf1);
    cudaGetSymbolAddress((void**)&x4n,  g_x4n);

    const int M = BATCH;
    dim3 blk(256);

    precompute_head<<<1, 512>>>(nW5, nb5, lW5, lb5, wreg);

    // node tower (relu after each of layers 1-4)
    gemm_btrans<true><<<dim3(256/128, M/128), blk>>>(node_x, nW1, nb1, buf0, M, 256, 256);
    gemm_btrans<true><<<dim3(512/128, M/128), blk>>>(buf0,   nW2, nb2, buf1, M, 512, 256);
    gemm_btrans<true><<<dim3(1024/128, M/128), blk>>>(buf1,  nW3, nb3, buf0, M, 1024, 512);
    gemm_btrans<true><<<dim3(512/128, M/128), blk>>>(buf0,   nW4, nb4, x4n,  M, 512, 1024);

    // layer tower
    gemm_btrans<true><<<dim3(256/128, M/128), blk>>>(layer_x, lW1, lb1, buf0, M, 256, 16);
    gemm_btrans<true><<<dim3(512/128, M/128), blk>>>(buf0,    lW2, lb2, buf1, M, 512, 256);
    gemm_btrans<true><<<dim3(1024/128, M/128), blk>>>(buf1,   lW3, lb3, buf0, M, 1024, 512);
    gemm_btrans<true><<<dim3(512/128, M/128), blk>>>(buf0,    lW4, lb4, buf1, M, 512, 1024);

    // fused collapsed head
    head_kernel<<<(BATCH * 32) / 256, blk>>>(x4n, buf1, out);
}

// round 7
// speedup vs baseline: 2.5218x; 2.5218x over previous
#include <cuda_runtime.h>
#include <cstdint>

#define BATCH 32768

// ---------------- scratch (static device globals; no allocs allowed) ----------------
__device__ __align__(16) float g_buf0[BATCH * 1024];
__device__ __align__(16) float g_buf1[BATCH * 1024];
__device__ __align__(16) float g_x4n [BATCH * 512];
__device__ __align__(16) float g_wn[512];
__device__ __align__(16) float g_wl[512];
__device__ float g_sc[2];   // [0]=bn (mean of nb5), [1]=bl (wreg . lb5)

// cvt.rna.tf32.f32: destination is a .b32 register (PTX ISA) -> "=r" constraint.
__device__ __forceinline__ uint32_t f32_to_tf32_rna(float x) {
    uint32_t r;
    asm("cvt.rna.tf32.f32 %0, %1;" : "=r"(r) : "f"(x));
    return r;
}

// ---------------- head-collapse precompute ----------------
// w_n[k] = mean_o nW5[o,k]          (nW5: [256,512])
// w_l[k] = sum_o wreg[o]*lW5[o,k]   (lW5: [256,512], wreg: [256])
__global__ void precompute_head(const float* __restrict__ nW5, const float* __restrict__ nb5,
                                const float* __restrict__ lW5, const float* __restrict__ lb5,
                                const float* __restrict__ wreg)
{
    int k = threadIdx.x;                // 512 threads
    float s1 = 0.f, s2 = 0.f;
    #pragma unroll 4
    for (int o = 0; o < 256; ++o) {
        s1 += nW5[o * 512 + k];
        s2 += wreg[o] * lW5[o * 512 + k];
    }
    g_wn[k] = s1 * (1.f / 256.f);
    g_wl[k] = s2;
    if (k == 0) {
        float b = 0.f;
        for (int o = 0; o < 256; ++o) b += nb5[o];
        g_sc[0] = b * (1.f / 256.f);
    }
    if (k == 1) {
        float b = 0.f;
        for (int o = 0; o < 256; ++o) b += wreg[o] * lb5[o];
        g_sc[1] = b;
    }
}

// ================= tf32 mma.sync GEMM =================
// C[M,N] = relu(A[M,K] @ W[N,K]^T + bias[N]); tf32(RNA) inputs, f32 accumulate.
// CTA 128x128, BK=32, 256 threads (8 warps: 2x4 grid, warp tile 64x32).
// mma.sync.m16n8k8 tf32 (sm_80+ baseline PTX -> legacy tensor path on sm_100).
// SMEM: row-padded stride 36 words -> conflict-free fragment LDS.
// Requires M%128==0, N%128==0. K=16 handled by zero-fill guard.

#define PAD_STRIDE 36                    // words per 32-col row (padded)
#define MAT_WORDS  (128 * PAD_STRIDE)    // 4608 words = 18432 B per matrix
#define BUF_WORDS  (2 * MAT_WORDS)       // A + B per buffer
#define SMEM_BYTES (2 * BUF_WORDS * 4)   // double-buffered: 73728 B

__device__ __forceinline__ void mma_tf32(float* c, const uint32_t* a, const uint32_t* b) {
    asm volatile(
        "mma.sync.aligned.m16n8k8.row.col.f32.tf32.tf32.f32 "
        "{%0,%1,%2,%3}, {%4,%5,%6,%7}, {%8,%9}, {%0,%1,%2,%3};"
        : "+f"(c[0]), "+f"(c[1]), "+f"(c[2]), "+f"(c[3])
        : "r"(a[0]), "r"(a[1]), "r"(a[2]), "r"(a[3]), "r"(b[0]), "r"(b[1]));
}

__global__ __launch_bounds__(256)
void gemm_mma(const float* __restrict__ A, const float* __restrict__ W,
              const float* __restrict__ bias, float* __restrict__ C,
              int M, int N, int K)
{
    extern __shared__ float sm[];   // [buf][A|B][128][PAD_STRIDE]

    const int t    = threadIdx.x;
    const int lane = t & 31;
    const int wid  = t >> 5;
    const int bm   = blockIdx.y * 128;
    const int bn   = blockIdx.x * 128;
    const int wm   = (wid >> 2) * 64;   // warp M offset (0 or 64)
    const int wn   = (wid & 3) * 32;    // warp N offset (0,32,64,96)
    const int gid  = lane >> 2;         // 0..7
    const int tg   = lane & 3;          // 0..3

    // global-load geometry: 1024 float4 per matrix tile; 4 per thread
    const int g_row = t >> 3;           // base row 0..31 (+32*j)
    const int g_c4  = (t & 7) << 2;     // k-offset 0,4,...,28

    float acc[4][4][4] = {};            // [mi][ni][c0..c3]
    float4 pa[4], pb[4];

    const int nkt = (K + 31) >> 5;

    // ---- helpers as lambdas ----
    auto ldg_tile = [&](int kt) {
        const int k0 = kt << 5;
        const bool ok = (k0 + g_c4 + 3) < K;   // full-vector in range?
        #pragma unroll
        for (int j = 0; j < 4; ++j) {
            const int row = g_row + (j << 5);
            float4 va = make_float4(0.f, 0.f, 0.f, 0.f);
            float4 vb = make_float4(0.f, 0.f, 0.f, 0.f);
            if (ok) {
                va = *(const float4*)(A + (long)(bm + row) * K + k0 + g_c4);
                vb = *(const float4*)(W + (long)(bn + row) * K + k0 + g_c4);
            }
            pa[j] = va; pb[j] = vb;
        }
    };
    auto sts_tile = [&](int buf) {
        float* as = sm + buf * BUF_WORDS;
        float* bs = as + MAT_WORDS;
        #pragma unroll
        for (int j = 0; j < 4; ++j) {
            const int row = g_row + (j << 5);
            float4 va, vb;
            va.x = __uint_as_float(f32_to_tf32_rna(pa[j].x));
            va.y = __uint_as_float(f32_to_tf32_rna(pa[j].y));
            va.z = __uint_as_float(f32_to_tf32_rna(pa[j].z));
            va.w = __uint_as_float(f32_to_tf32_rna(pa[j].w));
            vb.x = __uint_as_float(f32_to_tf32_rna(pb[j].x));
            vb.y = __uint_as_float(f32_to_tf32_rna(pb[j].y));
            vb.z = __uint_as_float(f32_to_tf32_rna(pb[j].z));
            vb.w = __uint_as_float(f32_to_tf32_rna(pb[j].w));
            *(float4*)(as + row * PAD_STRIDE + g_c4) = va;
            *(float4*)(bs + row * PAD_STRIDE + g_c4) = vb;
        }
    };

    // ---- prologue: fill buffer 0 ----
    ldg_tile(0);
    sts_tile(0);
    __syncthreads();

    // ---- main loop ----
    for (int kt = 0; kt < nkt; ++kt) {
        const int buf = kt & 1;
        if (kt + 1 < nkt) ldg_tile(kt + 1);   // overlap LDG with compute

        const float* as = sm + buf * BUF_WORDS;
        const float* bs = as + MAT_WORDS;

        #pragma unroll
        for (int ks = 0; ks < 4; ++ks) {
            const int kc = ks << 3;
            uint32_t af[4][4], bf[4][2];
            #pragma unroll
            for (int mi = 0; mi < 4; ++mi) {
                const int r0 = wm + (mi << 4) + gid;
                af[mi][0] = __float_as_uint(as[(r0    ) * PAD_STRIDE + kc + tg    ]);
                af[mi][1] = __float_as_uint(as[(r0 + 8) * PAD_STRIDE + kc + tg    ]);
                af[mi][2] = __float_as_uint(as[(r0    ) * PAD_STRIDE + kc + tg + 4]);
                af[mi][3] = __float_as_uint(as[(r0 + 8) * PAD_STRIDE + kc + tg + 4]);
            }
            #pragma unroll
            for (int ni = 0; ni < 4; ++ni) {
                const int rn = wn + (ni << 3) + gid;
                bf[ni][0] = __float_as_uint(bs[rn * PAD_STRIDE + kc + tg    ]);
                bf[ni][1] = __float_as_uint(bs[rn * PAD_STRIDE + kc + tg + 4]);
            }
            #pragma unroll
            for (int mi = 0; mi < 4; ++mi)
                #pragma unroll
                for (int ni = 0; ni < 4; ++ni)
                    mma_tf32(acc[mi][ni], af[mi], bf[ni]);
        }
        __syncthreads();

        if (kt + 1 < nkt) {
            sts_tile((kt + 1) & 1);
            __syncthreads();
        }
    }

    // ---- epilogue: bias + relu, STG.64 ----
    #pragma unroll
    for (int mi = 0; mi < 4; ++mi) {
        const long row0 = bm + wm + (mi << 4) + gid;
        const long row1 = row0 + 8;
        #pragma unroll
        for (int ni = 0; ni < 4; ++ni) {
            const int col = bn + wn + (ni << 3) + (tg << 1);
            const float b0 = __ldg(bias + col);
            const float b1 = __ldg(bias + col + 1);
            float2 lo, hi;
            lo.x = fmaxf(acc[mi][ni][0] + b0, 0.f);
            lo.y = fmaxf(acc[mi][ni][1] + b1, 0.f);
            hi.x = fmaxf(acc[mi][ni][2] + b0, 0.f);
            hi.y = fmaxf(acc[mi][ni][3] + b1, 0.f);
            *(float2*)(C + row0 * N + col) = lo;
            *(float2*)(C + row1 * N + col) = hi;
        }
    }
}

// ---------------- fused head: out[b] = (x4n[b].wn + bn) * (x4l[b].wl + bl) ----------------
__global__ __launch_bounds__(256)
void head_kernel(const float* __restrict__ xn, const float* __restrict__ xl,
                 float* __restrict__ out)
{
    int warp = (blockIdx.x * 256 + threadIdx.x) >> 5;
    int lane = threadIdx.x & 31;
    if (warp >= BATCH) return;

    const float4* pn = (const float4*)(xn + (long)warp * 512);
    const float4* pl = (const float4*)(xl + (long)warp * 512);
    const float4* wn = (const float4*)g_wn;
    const float4* wl = (const float4*)g_wl;

    float sn = 0.f, sl = 0.f;
    #pragma unroll
    for (int i = lane; i < 128; i += 32) {
        float4 a = pn[i], w = wn[i];
        sn += a.x * w.x + a.y * w.y + a.z * w.z + a.w * w.w;
        float4 b = pl[i], v = wl[i];
        sl += b.x * v.x + b.y * v.y + b.z * v.z + b.w * v.w;
    }
    #pragma unroll
    for (int off = 16; off > 0; off >>= 1) {
        sn += __shfl_xor_sync(0xffffffffu, sn, off);
        sl += __shfl_xor_sync(0xffffffffu, sl, off);
    }
    if (lane == 0)
        out[warp] = (sn + g_sc[0]) * (sl + g_sc[1]);
}

// ---------------- launch ----------------
extern "C" void kernel_launch(void* const* d_in, const int* in_sizes, int n_in,
                              void* d_out, int out_size)
{
    const float* node_x = (const float*)d_in[0];   // [B,256]
    const float* layer_x= (const float*)d_in[1];   // [B,16]
    const float* nW1 = (const float*)d_in[2];  const float* nb1 = (const float*)d_in[3];
    const float* nW2 = (const float*)d_in[4];  const float* nb2 = (const float*)d_in[5];
    const float* nW3 = (const float*)d_in[6];  const float* nb3 = (const float*)d_in[7];
    const float* nW4 = (const float*)d_in[8];  const float* nb4 = (const float*)d_in[9];
    const float* nW5 = (const float*)d_in[10]; const float* nb5 = (const float*)d_in[11];
    const float* lW1 = (const float*)d_in[12]; const float* lb1 = (const float*)d_in[13];
    const float* lW2 = (const float*)d_in[14]; const float* lb2 = (const float*)d_in[15];
    const float* lW3 = (const float*)d_in[16]; const float* lb3 = (const float*)d_in[17];
    const float* lW4 = (const float*)d_in[18]; const float* lb4 = (const float*)d_in[19];
    const float* lW5 = (const float*)d_in[20]; const float* lb5 = (const float*)d_in[21];
    const float* wreg= (const float*)d_in[22]; // [256]
    float* out = (float*)d_out;

    float *buf0, *buf1, *x4n;
    cudaGetSymbolAddress((void**)&buf0, g_buf0);
    cudaGetSymbolAddress((void**)&buf1, g_buf1);
    cudaGetSymbolAddress((void**)&x4n,  g_x4n);

    const int M = BATCH;
    cudaFuncSetAttribute(gemm_mma, cudaFuncAttributeMaxDynamicSharedMemorySize, SMEM_BYTES);

    dim3 blk(256);

    precompute_head<<<1, 512>>>(nW5, nb5, lW5, lb5, wreg);

    // node tower (relu after layers 1-4; layer 5 collapsed into head)
    gemm_mma<<<dim3(256/128,  M/128), blk, SMEM_BYTES>>>(node_x, nW1, nb1, buf0, M, 256, 256);
    gemm_mma<<<dim3(512/128,  M/128), blk, SMEM_BYTES>>>(buf0,   nW2, nb2, buf1, M, 512, 256);
    gemm_mma<<<dim3(1024/128, M/128), blk, SMEM_BYTES>>>(buf1,   nW3, nb3, buf0, M, 1024, 512);
    gemm_mma<<<dim3(512/128,  M/128), blk, SMEM_BYTES>>>(buf0,   nW4, nb4, x4n,  M, 512, 1024);

    // layer tower
    gemm_mma<<<dim3(256/128,  M/128), blk, SMEM_BYTES>>>(layer_x, lW1, lb1, buf0, M, 256, 16);
    gemm_mma<<<dim3(512/128,  M/128), blk, SMEM_BYTES>>>(buf0,    lW2, lb2, buf1, M, 512, 256);
    gemm_mma<<<dim3(1024/128, M/128), blk, SMEM_BYTES>>>(buf1,    lW3, lb3, buf0, M, 1024, 512);
    gemm_mma<<<dim3(512/128,  M/128), blk, SMEM_BYTES>>>(buf0,    lW4, lb4, buf1, M, 512, 1024);

    // fused collapsed head
    head_kernel<<<(BATCH * 32) / 256, blk>>>(x4n, buf1, out);
}

// round 8
// speedup vs baseline: 3.3980x; 1.3474x over previous
#include <cuda_runtime.h>
#include <cstdint>

#define BATCH 32768

// ---------------- scratch (static device globals; no allocs allowed) ----------------
__device__ __align__(16) float g_buf0[BATCH * 1024];
__device__ __align__(16) float g_buf1[BATCH * 1024];
__device__ __align__(16) float g_x4n [BATCH * 512];
__device__ __align__(16) float g_xn  [BATCH * 256];   // tf32-rounded node_x
__device__ __align__(16) float g_xl  [BATCH * 16];    // tf32-rounded layer_x
__device__ __align__(16) float g_wt  [2428928];       // tf32-rounded weights (8 mats)
__device__ __align__(16) float g_wn[512];
__device__ __align__(16) float g_wl[512];
__device__ float g_sc[2];   // [0]=bn (mean of nb5), [1]=bl (wreg . lb5)

// weight offsets inside g_wt
#define OFF_NW1 0
#define OFF_NW2 65536
#define OFF_NW3 196608
#define OFF_NW4 720896
#define OFF_LW1 1245184
#define OFF_LW2 1249280
#define OFF_LW3 1380352
#define OFF_LW4 1904640

// cvt.rna.tf32.f32: destination is a .b32 register -> "=r".
__device__ __forceinline__ uint32_t f32_to_tf32_rna(float x) {
    uint32_t r;
    asm("cvt.rna.tf32.f32 %0, %1;" : "=r"(r) : "f"(x));
    return r;
}
__device__ __forceinline__ float tf32r(float x) {
    return __uint_as_float(f32_to_tf32_rna(x));
}

__device__ __forceinline__ uint32_t smem_u32(const void* p) {
    uint32_t a;
    asm("{ .reg .u64 t; cvta.to.shared.u64 t, %1; cvt.u32.u64 %0, t; }" : "=r"(a) : "l"(p));
    return a;
}

// cp.async 16B with register src-size (0 => zero-fill 16B)
__device__ __forceinline__ void cp16(uint32_t dst, const void* src, int src_size) {
    asm volatile("cp.async.cg.shared.global [%0], [%1], 16, %2;"
                 :: "r"(dst), "l"(src), "r"(src_size));
}
#define CP_COMMIT() asm volatile("cp.async.commit_group;" ::: "memory")
#define CP_WAIT0()  asm volatile("cp.async.wait_group 0;" ::: "memory")
#define CP_WAIT1()  asm volatile("cp.async.wait_group 1;" ::: "memory")

// ---------------- tf32-RNA rounding prepass ----------------
__global__ void cvt_rna_kernel(const float* __restrict__ src, float* __restrict__ dst, int n)
{
    int i = (blockIdx.x * 256 + threadIdx.x) * 4;
    if (i < n) {
        float4 v = *(const float4*)(src + i);
        v.x = tf32r(v.x); v.y = tf32r(v.y); v.z = tf32r(v.z); v.w = tf32r(v.w);
        *(float4*)(dst + i) = v;
    }
}

// ---------------- head-collapse precompute ----------------
// w_n[k] = mean_o nW5[o,k]; w_l[k] = sum_o wreg[o]*lW5[o,k]
__global__ void precompute_head(const float* __restrict__ nW5, const float* __restrict__ nb5,
                                const float* __restrict__ lW5, const float* __restrict__ lb5,
                                const float* __restrict__ wreg)
{
    int k = threadIdx.x;                // 512 threads
    float s1 = 0.f, s2 = 0.f;
    #pragma unroll 4
    for (int o = 0; o < 256; ++o) {
        s1 += nW5[o * 512 + k];
        s2 += wreg[o] * lW5[o * 512 + k];
    }
    g_wn[k] = s1 * (1.f / 256.f);
    g_wl[k] = s2;
    if (k == 0) {
        float b = 0.f;
        for (int o = 0; o < 256; ++o) b += nb5[o];
        g_sc[0] = b * (1.f / 256.f);
    }
    if (k == 1) {
        float b = 0.f;
        for (int o = 0; o < 256; ++o) b += wreg[o] * lb5[o];
        g_sc[1] = b;
    }
}

// ================= tf32 mma.sync GEMM v2 (cp.async, no mainloop cvt) =================
// C[M,N] = tf32r(relu(A @ W^T + bias)); A, W pre-rounded to tf32 bit patterns.
// CTA 128x128, BK=32, 256 threads (8 warps, 2x4, warp tile 64x32), 2 CTAs/SM.

#define PAD_STRIDE 36                    // words per 32-col row (padded)
#define MAT_WORDS  (128 * PAD_STRIDE)    // 4608 words
#define MAT_BYTES  (MAT_WORDS * 4)       // 18432 B
#define BUF_BYTES  (2 * MAT_BYTES)       // A + B per buffer: 36864 B
#define SMEM_BYTES (2 * BUF_BYTES)       // double-buffered: 73728 B

__device__ __forceinline__ void mma_tf32(float* c, const uint32_t* a, const uint32_t* b) {
    asm volatile(
        "mma.sync.aligned.m16n8k8.row.col.f32.tf32.tf32.f32 "
        "{%0,%1,%2,%3}, {%4,%5,%6,%7}, {%8,%9}, {%0,%1,%2,%3};"
        : "+f"(c[0]), "+f"(c[1]), "+f"(c[2]), "+f"(c[3])
        : "r"(a[0]), "r"(a[1]), "r"(a[2]), "r"(a[3]), "r"(b[0]), "r"(b[1]));
}

__global__ __launch_bounds__(256, 2)
void gemm_mma(const float* __restrict__ A, const float* __restrict__ W,
              const float* __restrict__ bias, float* __restrict__ C,
              int M, int N, int K)
{
    extern __shared__ float sm[];   // [buf][A|B][128][PAD_STRIDE]

    const int t    = threadIdx.x;
    const int lane = t & 31;
    const int wid  = t >> 5;
    const int bm   = blockIdx.y * 128;
    const int bn   = blockIdx.x * 128;
    const int wm   = (wid >> 2) * 64;   // warp M offset (0 or 64)
    const int wn   = (wid & 3) * 32;    // warp N offset (0,32,64,96)
    const int gid  = lane >> 2;         // 0..7
    const int tg   = lane & 3;          // 0..3

    // async-copy geometry: 1024 x 16B per matrix tile; 4 per thread per matrix
    const int g_row = t >> 3;           // base row 0..31 (+32*j)
    const int g_c4  = (t & 7) << 2;     // k word offset 0,4,...,28

    const uint32_t sbase = smem_u32(sm);
    const uint32_t d_off = (uint32_t)(g_row * PAD_STRIDE + g_c4) * 4;

    float acc[4][4][4] = {};            // [mi][ni][c0..c3]
    const int nkt = (K + 31) >> 5;

    auto cp_tile = [&](int kt, int buf) {
        const int k0 = kt << 5;
        const bool ok = (k0 + g_c4 + 3) < K;
        const int sz = ok ? 16 : 0;
        const int koff = ok ? (k0 + g_c4) : 0;       // safe base when zero-filling
        const uint32_t dA = sbase + buf * BUF_BYTES + d_off;
        const uint32_t dB = dA + MAT_BYTES;
        const float* Ap = A + (long)(bm + g_row) * K + koff;
        const float* Wp = W + (long)(bn + g_row) * K + koff;
        #pragma unroll
        for (int j = 0; j < 4; ++j) {
            cp16(dA + j * 32 * (PAD_STRIDE * 4), Ap + (long)j * 32 * K, sz);
            cp16(dB + j * 32 * (PAD_STRIDE * 4), Wp + (long)j * 32 * K, sz);
        }
    };

    // ---- prologue ----
    cp_tile(0, 0);
    CP_COMMIT();

    // ---- main loop ----
    for (int kt = 0; kt < nkt; ++kt) {
        const int buf = kt & 1;
        if (kt + 1 < nkt) {
            cp_tile(kt + 1, buf ^ 1);
            CP_COMMIT();
            CP_WAIT1();                 // current buffer's group complete
        } else {
            CP_WAIT0();
        }
        __syncthreads();

        const float* as = sm + buf * (BUF_BYTES / 4);
        const float* bs = as + MAT_WORDS;

        #pragma unroll
        for (int ks = 0; ks < 4; ++ks) {
            const int kc = ks << 3;
            uint32_t af[4][4], bf[4][2];
            #pragma unroll
            for (int mi = 0; mi < 4; ++mi) {
                const int r0 = wm + (mi << 4) + gid;
                af[mi][0] = __float_as_uint(as[(r0    ) * PAD_STRIDE + kc + tg    ]);
                af[mi][1] = __float_as_uint(as[(r0 + 8) * PAD_STRIDE + kc + tg    ]);
                af[mi][2] = __float_as_uint(as[(r0    ) * PAD_STRIDE + kc + tg + 4]);
                af[mi][3] = __float_as_uint(as[(r0 + 8) * PAD_STRIDE + kc + tg + 4]);
            }
            #pragma unroll
            for (int ni = 0; ni < 4; ++ni) {
                const int rn = wn + (ni << 3) + gid;
                bf[ni][0] = __float_as_uint(bs[rn * PAD_STRIDE + kc + tg    ]);
                bf[ni][1] = __float_as_uint(bs[rn * PAD_STRIDE + kc + tg + 4]);
            }
            #pragma unroll
            for (int mi = 0; mi < 4; ++mi)
                #pragma unroll
                for (int ni = 0; ni < 4; ++ni)
                    mma_tf32(acc[mi][ni], af[mi], bf[ni]);
        }
        __syncthreads();   // all reads of buf done before it is overwritten next iter
    }

    // ---- epilogue: bias + relu + tf32-RNA round (feeds next layer / head) ----
    #pragma unroll
    for (int mi = 0; mi < 4; ++mi) {
        const long row0 = bm + wm + (mi << 4) + gid;
        const long row1 = row0 + 8;
        #pragma unroll
        for (int ni = 0; ni < 4; ++ni) {
            const int col = bn + wn + (ni << 3) + (tg << 1);
            const float b0 = __ldg(bias + col);
            const float b1 = __ldg(bias + col + 1);
            float2 lo, hi;
            lo.x = tf32r(fmaxf(acc[mi][ni][0] + b0, 0.f));
            lo.y = tf32r(fmaxf(acc[mi][ni][1] + b1, 0.f));
            hi.x = tf32r(fmaxf(acc[mi][ni][2] + b0, 0.f));
            hi.y = tf32r(fmaxf(acc[mi][ni][3] + b1, 0.f));
            *(float2*)(C + row0 * N + col) = lo;
            *(float2*)(C + row1 * N + col) = hi;
        }
    }
}

// ---------------- fused head: out[b] = (x4n[b].wn + bn) * (x4l[b].wl + bl) ----------------
__global__ __launch_bounds__(256)
void head_kernel(const float* __restrict__ xn, const float* __restrict__ xl,
                 float* __restrict__ out)
{
    int warp = (blockIdx.x * 256 + threadIdx.x) >> 5;
    int lane = threadIdx.x & 31;
    if (warp >= BATCH) return;

    const float4* pn = (const float4*)(xn + (long)warp * 512);
    const float4* pl = (const float4*)(xl + (long)warp * 512);
    const float4* wn = (const float4*)g_wn;
    const float4* wl = (const float4*)g_wl;

    float sn = 0.f, sl = 0.f;
    #pragma unroll
    for (int i = lane; i < 128; i += 32) {
        float4 a = pn[i], w = wn[i];
        sn += a.x * w.x + a.y * w.y + a.z * w.z + a.w * w.w;
        float4 b = pl[i], v = wl[i];
        sl += b.x * v.x + b.y * v.y + b.z * v.z + b.w * v.w;
    }
    #pragma unroll
    for (int off = 16; off > 0; off >>= 1) {
        sn += __shfl_xor_sync(0xffffffffu, sn, off);
        sl += __shfl_xor_sync(0xffffffffu, sl, off);
    }
    if (lane == 0)
        out[warp] = (sn + g_sc[0]) * (sl + g_sc[1]);
}

// ---------------- launch ----------------
static inline void cvt_launch(const float* src, float* dst, int n) {
    cvt_rna_kernel<<<(n / 4 + 255) / 256, 256>>>(src, dst, n);
}

extern "C" void kernel_launch(void* const* d_in, const int* in_sizes, int n_in,
                              void* d_out, int out_size)
{
    const float* node_x = (const float*)d_in[0];   // [B,256]
    const float* layer_x= (const float*)d_in[1];   // [B,16]
    const float* nW1 = (const float*)d_in[2];  const float* nb1 = (const float*)d_in[3];
    const float* nW2 = (const float*)d_in[4];  const float* nb2 = (const float*)d_in[5];
    const float* nW3 = (const float*)d_in[6];  const float* nb3 = (const float*)d_in[7];
    const float* nW4 = (const float*)d_in[8];  const float* nb4 = (const float*)d_in[9];
    const float* nW5 = (const float*)d_in[10]; const float* nb5 = (const float*)d_in[11];
    const float* lW1 = (const float*)d_in[12]; const float* lb1 = (const float*)d_in[13];
    const float* lW2 = (const float*)d_in[14]; const float* lb2 = (const float*)d_in[15];
    const float* lW3 = (const float*)d_in[16]; const float* lb3 = (const float*)d_in[17];
    const float* lW4 = (const float*)d_in[18]; const float* lb4 = (const float*)d_in[19];
    const float* lW5 = (const float*)d_in[20]; const float* lb5 = (const float*)d_in[21];
    const float* wreg= (const float*)d_in[22]; // [256]
    float* out = (float*)d_out;

    float *buf0, *buf1, *x4n, *xn, *xl, *wt;
    cudaGetSymbolAddress((void**)&buf0, g_buf0);
    cudaGetSymbolAddress((void**)&buf1, g_buf1);
    cudaGetSymbolAddress((void**)&x4n,  g_x4n);
    cudaGetSymbolAddress((void**)&xn,   g_xn);
    cudaGetSymbolAddress((void**)&xl,   g_xl);
    cudaGetSymbolAddress((void**)&wt,   g_wt);

    const int M = BATCH;
    cudaFuncSetAttribute(gemm_mma, cudaFuncAttributeMaxDynamicSharedMemorySize, SMEM_BYTES);

    dim3 blk(256);

    precompute_head<<<1, 512>>>(nW5, nb5, lW5, lb5, wreg);

    // tf32-RNA prepass: inputs + weights (outputs are rounded in GEMM epilogues)
    cvt_launch(node_x,  xn, BATCH * 256);
    cvt_launch(layer_x, xl, BATCH * 16);
    cvt_launch(nW1, wt + OFF_NW1, 256 * 256);
    cvt_launch(nW2, wt + OFF_NW2, 512 * 256);
    cvt_launch(nW3, wt + OFF_NW3, 1024 * 512);
    cvt_launch(nW4, wt + OFF_NW4, 512 * 1024);
    cvt_launch(lW1, wt + OFF_LW1, 256 * 16);
    cvt_launch(lW2, wt + OFF_LW2, 512 * 256);
    cvt_launch(lW3, wt + OFF_LW3, 1024 * 512);
    cvt_launch(lW4, wt + OFF_LW4, 512 * 1024);

    // node tower (relu after layers 1-4; layer 5 collapsed into head)
    gemm_mma<<<dim3(256/128,  M/128), blk, SMEM_BYTES>>>(xn,   wt + OFF_NW1, nb1, buf0, M, 256, 256);
    gemm_mma<<<dim3(512/128,  M/128), blk, SMEM_BYTES>>>(buf0, wt + OFF_NW2, nb2, buf1, M, 512, 256);
    gemm_mma<<<dim3(1024/128, M/128), blk, SMEM_BYTES>>>(buf1, wt + OFF_NW3, nb3, buf0, M, 1024, 512);
    gemm_mma<<<dim3(512/128,  M/128), blk, SMEM_BYTES>>>(buf0, wt + OFF_NW4, nb4, x4n,  M, 512, 1024);

    // layer tower
    gemm_mma<<<dim3(256/128,  M/128), blk, SMEM_BYTES>>>(xl,   wt + OFF_LW1, lb1, buf0, M, 256, 16);
    gemm_mma<<<dim3(512/128,  M/128), blk, SMEM_BYTES>>>(buf0, wt + OFF_LW2, lb2, buf1, M, 512, 256);
    gemm_mma<<<dim3(1024/128, M/128), blk, SMEM_BYTES>>>(buf1, wt + OFF_LW3, lb3, buf0, M, 1024, 512);
    gemm_mma<<<dim3(512/128,  M/128), blk, SMEM_BYTES>>>(buf0, wt + OFF_LW4, lb4, buf1, M, 512, 1024);

    // fused collapsed head
    head_kernel<<<(BATCH * 32) / 256, blk>>>(x4n, buf1, out);
}